// round 1
// baseline (speedup 1.0000x reference)
#include <cuda_runtime.h>

// ---------------------------------------------------------------------------
// SpatialTransformer: full self-attention block, fp32 baseline (Round 0)
//   Q = x @ Wq^T + bq              [B*SQ, C]
//   K = ce @ Wk^T + bk             [B*SKV, C]
//   V = ce @ Wv^T + bv             [B*SKV, C]
//   S = (Q @ K^T) / sqrt(C)        per batch [SQ, SKV]
//   P = softmax_rows(S)            in place
//   A = P @ V                      per batch [SQ, C]
//   out = (x + A) @ Wo^T + bo      [B*SQ, C]
// ---------------------------------------------------------------------------

#define Cdim  1024
#define Bdim  4
#define SQdim 2048
#define SKVdim 2048

// Scratch (device-global; no allocations allowed)
__device__ float g_Q  [(long long)Bdim * SQdim  * Cdim];   // 8.39M
__device__ float g_K  [(long long)Bdim * SKVdim * Cdim];   // 8.39M
__device__ float g_V  [(long long)Bdim * SKVdim * Cdim];   // 8.39M
__device__ float g_S  [(long long)Bdim * SQdim  * SKVdim]; // 16.8M
__device__ float g_ATT[(long long)Bdim * SQdim  * Cdim];   // 8.39M

#define BM 128
#define BN 128
#define BKD 8

// C[M,N] = scale * (A[M,K](+Aadd) @ B) + bias
//   TRANSB=1: B is [N,K] row-major (NT gemm, inner dim contiguous both sides)
//   TRANSB=0: B is [K,N] row-major (NN gemm)
// Batched via blockIdx.z with element strides sA/sB/sC.
// REQUIREMENTS (all satisfied by our shapes): M%128==0, N%128==0, K%8==0.
template<bool TRANSB, bool HAS_ADD, bool HAS_BIAS>
__global__ __launch_bounds__(256)
void sgemm_kernel(const float* __restrict__ A, const float* __restrict__ Aadd,
                  const float* __restrict__ B, const float* __restrict__ bias,
                  float* __restrict__ Cout,
                  int M, int N, int K,
                  long long sA, long long sB, long long sC, float scale)
{
    A    += (long long)blockIdx.z * sA;
    if (HAS_ADD) Aadd += (long long)blockIdx.z * sA;
    B    += (long long)blockIdx.z * sB;
    Cout += (long long)blockIdx.z * sC;

    __shared__ float As[BKD][BM];
    __shared__ float Bs[BKD][BN];

    const int tid = threadIdx.x;
    const int tx  = tid & 15;        // 0..15
    const int ty  = tid >> 4;        // 0..15

    const int m0 = blockIdx.y * BM;
    const int n0 = blockIdx.x * BN;

    // tile-load indices: 128 rows x 8 cols per operand, one float4 per thread
    const int aRow = tid >> 1;          // 0..127
    const int aCol = (tid & 1) * 4;     // 0 or 4

    float acc[8][8];
    #pragma unroll
    for (int i = 0; i < 8; i++)
        #pragma unroll
        for (int j = 0; j < 8; j++) acc[i][j] = 0.f;

    for (int k0 = 0; k0 < K; k0 += BKD) {
        // ---- load A tile (transposed into As[k][m]) ----
        {
            long long idx = (long long)(m0 + aRow) * K + k0 + aCol;
            float4 av = *(const float4*)(A + idx);
            if (HAS_ADD) {
                float4 rv = *(const float4*)(Aadd + idx);
                av.x += rv.x; av.y += rv.y; av.z += rv.z; av.w += rv.w;
            }
            As[aCol + 0][aRow] = av.x;
            As[aCol + 1][aRow] = av.y;
            As[aCol + 2][aRow] = av.z;
            As[aCol + 3][aRow] = av.w;
        }
        // ---- load B tile into Bs[k][n] ----
        if (TRANSB) {
            long long idx = (long long)(n0 + aRow) * K + k0 + aCol;
            float4 bv = *(const float4*)(B + idx);
            Bs[aCol + 0][aRow] = bv.x;
            Bs[aCol + 1][aRow] = bv.y;
            Bs[aCol + 2][aRow] = bv.z;
            Bs[aCol + 3][aRow] = bv.w;
        } else {
            const int bRow = tid >> 5;          // 0..7  (k)
            const int bCol = (tid & 31) * 4;    // 0..124 (n)
            long long idx = (long long)(k0 + bRow) * N + n0 + bCol;
            *(float4*)&Bs[bRow][bCol] = *(const float4*)(B + idx);
        }
        __syncthreads();

        // ---- 128x128x8 register-tiled FMA, quadrant layout (conflict-free) ----
        #pragma unroll
        for (int k = 0; k < BKD; k++) {
            float ra[8], rb[8];
            *(float4*)&ra[0] = *(const float4*)&As[k][ty * 4];
            *(float4*)&ra[4] = *(const float4*)&As[k][64 + ty * 4];
            *(float4*)&rb[0] = *(const float4*)&Bs[k][tx * 4];
            *(float4*)&rb[4] = *(const float4*)&Bs[k][64 + tx * 4];
            #pragma unroll
            for (int i = 0; i < 8; i++)
                #pragma unroll
                for (int j = 0; j < 8; j++)
                    acc[i][j] += ra[i] * rb[j];
        }
        __syncthreads();
    }

    // ---- epilogue: scale, bias, store (float4, coalesced) ----
    #pragma unroll
    for (int ih = 0; ih < 2; ih++) {
        #pragma unroll
        for (int i = 0; i < 4; i++) {
            int r = m0 + ih * 64 + ty * 4 + i;
            #pragma unroll
            for (int jh = 0; jh < 2; jh++) {
                int c = n0 + jh * 64 + tx * 4;
                float4 v;
                v.x = acc[ih * 4 + i][jh * 4 + 0] * scale;
                v.y = acc[ih * 4 + i][jh * 4 + 1] * scale;
                v.z = acc[ih * 4 + i][jh * 4 + 2] * scale;
                v.w = acc[ih * 4 + i][jh * 4 + 3] * scale;
                if (HAS_BIAS) {
                    v.x += bias[c + 0];
                    v.y += bias[c + 1];
                    v.z += bias[c + 2];
                    v.w += bias[c + 3];
                }
                *(float4*)(Cout + (long long)r * N + c) = v;
            }
        }
    }
}

// Row softmax, one block (256 threads) per row.
__global__ __launch_bounds__(256)
void softmax_rows(float* __restrict__ S, int ncols)
{
    long long row = blockIdx.x;
    float* p = S + row * (long long)ncols;
    __shared__ float red[256];
    const int tid = threadIdx.x;

    float m = -3.4e38f;
    for (int i = tid; i < ncols; i += 256) m = fmaxf(m, p[i]);
    red[tid] = m; __syncthreads();
    #pragma unroll
    for (int s = 128; s > 0; s >>= 1) {
        if (tid < s) red[tid] = fmaxf(red[tid], red[tid + s]);
        __syncthreads();
    }
    m = red[0];
    __syncthreads();

    float sum = 0.f;
    for (int i = tid; i < ncols; i += 256) {
        float e = __expf(p[i] - m);
        p[i] = e;
        sum += e;
    }
    red[tid] = sum; __syncthreads();
    #pragma unroll
    for (int s = 128; s > 0; s >>= 1) {
        if (tid < s) red[tid] += red[tid + s];
        __syncthreads();
    }
    float inv = 1.0f / red[0];
    for (int i = tid; i < ncols; i += 256) p[i] *= inv;
}

extern "C" void kernel_launch(void* const* d_in, const int* in_sizes, int n_in,
                              void* d_out, int out_size)
{
    const float* x  = (const float*)d_in[0];
    const float* ce = (const float*)d_in[1];
    const float* Wq = (const float*)d_in[2];
    const float* bq = (const float*)d_in[3];
    const float* Wk = (const float*)d_in[4];
    const float* bk = (const float*)d_in[5];
    const float* Wv = (const float*)d_in[6];
    const float* bv = (const float*)d_in[7];
    const float* Wo = (const float*)d_in[8];
    const float* bo = (const float*)d_in[9];
    float* out = (float*)d_out;

    float *Q, *K, *V, *S, *ATT;
    cudaGetSymbolAddress((void**)&Q,   g_Q);
    cudaGetSymbolAddress((void**)&K,   g_K);
    cudaGetSymbolAddress((void**)&V,   g_V);
    cudaGetSymbolAddress((void**)&S,   g_S);
    cudaGetSymbolAddress((void**)&ATT, g_ATT);

    const int M  = Bdim * SQdim;            // 8192
    const float inv_sqrt_c = 0.03125f;      // 1/sqrt(1024)

    dim3 blk(256);
    dim3 gProj(Cdim / BN, M / BM, 1);                 // (8, 64)
    dim3 gScore(SKVdim / BN, SQdim / BM, Bdim);       // (16, 16, 4)
    dim3 gAtt(Cdim / BN, SQdim / BM, Bdim);           // (8, 16, 4)

    // 1-3: projections  (NT, bias)
    sgemm_kernel<true, false, true><<<gProj, blk>>>(
        x, nullptr, Wq, bq, Q, M, Cdim, Cdim, 0, 0, 0, 1.0f);
    sgemm_kernel<true, false, true><<<gProj, blk>>>(
        ce, nullptr, Wk, bk, K, M, Cdim, Cdim, 0, 0, 0, 1.0f);
    sgemm_kernel<true, false, true><<<gProj, blk>>>(
        ce, nullptr, Wv, bv, V, M, Cdim, Cdim, 0, 0, 0, 1.0f);

    // 4: scores = (Q @ K^T) / sqrt(C)   (NT, batched, no bias)
    sgemm_kernel<true, false, false><<<gScore, blk>>>(
        Q, nullptr, K, nullptr, S,
        SQdim, SKVdim, Cdim,
        (long long)SQdim * Cdim, (long long)SKVdim * Cdim,
        (long long)SQdim * SKVdim, inv_sqrt_c);

    // 5: softmax rows (in place)
    softmax_rows<<<Bdim * SQdim, blk>>>(S, SKVdim);

    // 6: attended = P @ V   (NN, batched, no bias)
    sgemm_kernel<false, false, false><<<gAtt, blk>>>(
        S, nullptr, V, nullptr, ATT,
        SQdim, Cdim, SKVdim,
        (long long)SQdim * SKVdim, (long long)SKVdim * Cdim,
        (long long)SQdim * Cdim, 1.0f);

    // 7: out = (x + attended) @ Wo^T + bo   (NT, residual fused, bias)
    sgemm_kernel<true, true, true><<<gProj, blk>>>(
        ATT, x, Wo, bo, out, M, Cdim, Cdim, 0, 0, 0, 1.0f);
}

// round 3
// speedup vs baseline: 2.5094x; 2.5094x over previous
#include <cuda_runtime.h>
#include <cstdint>

// ---------------------------------------------------------------------------
// SpatialTransformer via mma.sync TF32 (Round 3)
//   (tcgen05 unavailable: harness ptxas targets compute_103, not sm_103a)
//   Q  = x  @ Wq^T + bq                      NT, bias-N
//   K  = ce @ Wk^T + bk                      NT, bias-N
//   Vt = Wv @ ce^T + bv  (= V^T)             NT, bias-M  -> [C, B*SKV]
//   S  = (Q @ K^T) / 32                      NT, batched
//   P  = softmax_rows(S)
//   At = P @ Vt^T + x    (residual fused)    NT, batched, +Add
//   out= At @ Wo^T + bo                      NT, bias-N
// GEMM kernel: CTA 128x128, BK=32, 8 warps x (64x32 warp tile),
// m16n8k8.tf32 fragments, double-buffered SMEM, 1 sync/iter, reg prefetch.
// fp32 -> tf32 with cvt.rna at SMEM store (avoids truncation bias).
// ---------------------------------------------------------------------------

#define Cdim  1024
#define Bdim  4
#define SQdim 2048
#define SKVdim 2048

__device__ float g_Q [(long long)Bdim * SQdim  * Cdim];
__device__ float g_K [(long long)Bdim * SKVdim * Cdim];
__device__ float g_Vt[(long long)Cdim * Bdim  * SKVdim];
__device__ float g_S [(long long)Bdim * SQdim  * SKVdim];
__device__ float g_At[(long long)Bdim * SQdim  * Cdim];

__device__ __forceinline__ uint32_t f2tf(float f){
    uint32_t r; asm("cvt.rna.tf32.f32 %0, %1;" : "=r"(r) : "f"(f)); return r;
}

__device__ __forceinline__ void mma8(float* d, const uint32_t* a, const uint32_t* b){
    asm volatile("mma.sync.aligned.m16n8k8.row.col.f32.tf32.tf32.f32 "
        "{%0,%1,%2,%3}, {%4,%5,%6,%7}, {%8,%9}, {%0,%1,%2,%3};"
        : "+f"(d[0]), "+f"(d[1]), "+f"(d[2]), "+f"(d[3])
        : "r"(a[0]), "r"(a[1]), "r"(a[2]), "r"(a[3]), "r"(b[0]), "r"(b[1]));
}

// SMEM element-index layout (floats): tiles stride 36 floats/row (bank-safe, 16B aligned)
#define TSTR 36
#define A0_OFF 0
#define A1_OFF 4608          // 128*36
#define B0_OFF 9216
#define B1_OFF 13824
#define SMEM_FLOATS 18432    // 73728 bytes
#define SMEM_BYTES  73728
#define CSTR 132             // epilogue staging stride (16B aligned rows: 528B)

// D[128 x 128] tile of: scale*(A @ B^T) [+bias_N | +bias_M] [+Add]
// A: [*, K] row-major (lda), B: [*, K] row-major (ldb), C row-major (ldc).
// Requires M%128==0, N%128==0, K%32==0 (true for all our shapes).
template<bool BN_, bool BM_, bool ADD_>
__global__ __launch_bounds__(256)
void gemm_mma(const float* __restrict__ A, const float* __restrict__ B,
              const float* __restrict__ bias, const float* __restrict__ Add,
              float* __restrict__ C,
              int lda, int ldb, int ldc, int NK,
              long long sA, long long sB, long long sC, long long sAdd,
              float scale)
{
    extern __shared__ float sm[];
    const int tid = threadIdx.x, wid = tid >> 5, lane = tid & 31;

    A += (long long)blockIdx.z * sA;
    B += (long long)blockIdx.z * sB;
    C += (long long)blockIdx.z * sC;
    if (ADD_) Add += (long long)blockIdx.z * sAdd;

    const int m0 = blockIdx.y * 128;
    const int n0 = blockIdx.x * 128;

    // ---- loader mapping: each thread = 1 row-half of A and of B (4 float4 each) ----
    const int lrow = tid >> 1;              // 0..127
    const int lcol = (tid & 1) * 16;        // 0 or 16
    const float* ap = A + (long long)(m0 + lrow) * lda + lcol;
    const float* bp = B + (long long)(n0 + lrow) * ldb + lcol;
    const int soff = lrow * TSTR + lcol;    // float index within tile

    // ---- warp tile mapping ----
    const int wm = (wid & 1) * 64;          // warp row offset
    const int wn = (wid >> 1) * 32;         // warp col offset
    const int qr = lane >> 2;               // quad row 0..7
    const int qc = lane & 3;                // quad col 0..3

    float acc[4][4][4];
    #pragma unroll
    for (int mi = 0; mi < 4; mi++)
        #pragma unroll
        for (int ni = 0; ni < 4; ni++)
            #pragma unroll
            for (int j = 0; j < 4; j++) acc[mi][ni][j] = 0.f;

    float4 ra[4], rb[4];
    #pragma unroll
    for (int i = 0; i < 4; i++) { ra[i] = *(const float4*)(ap + i * 4); }
    #pragma unroll
    for (int i = 0; i < 4; i++) { rb[i] = *(const float4*)(bp + i * 4); }

    for (int k = 0; k < NK; k++) {
        const int buf = k & 1;
        float* as = sm + (buf ? A1_OFF : A0_OFF);
        float* bs = sm + (buf ? B1_OFF : B0_OFF);

        // cvt.rna -> tf32 bits, store as float4
        #pragma unroll
        for (int i = 0; i < 4; i++) {
            float4 v;
            v.x = __uint_as_float(f2tf(ra[i].x));
            v.y = __uint_as_float(f2tf(ra[i].y));
            v.z = __uint_as_float(f2tf(ra[i].z));
            v.w = __uint_as_float(f2tf(ra[i].w));
            *(float4*)(as + soff + i * 4) = v;
        }
        #pragma unroll
        for (int i = 0; i < 4; i++) {
            float4 v;
            v.x = __uint_as_float(f2tf(rb[i].x));
            v.y = __uint_as_float(f2tf(rb[i].y));
            v.z = __uint_as_float(f2tf(rb[i].z));
            v.w = __uint_as_float(f2tf(rb[i].w));
            *(float4*)(bs + soff + i * 4) = v;
        }
        // prefetch next k-tile while this one is consumed
        if (k + 1 < NK) {
            const int k0 = (k + 1) * 32;
            #pragma unroll
            for (int i = 0; i < 4; i++) ra[i] = *(const float4*)(ap + k0 + i * 4);
            #pragma unroll
            for (int i = 0; i < 4; i++) rb[i] = *(const float4*)(bp + k0 + i * 4);
        }
        __syncthreads();

        // ---- 4 k-steps of m16n8k8 ----
        #pragma unroll
        for (int s = 0; s < 4; s++) {
            const int kk = s * 8;
            uint32_t afr[4][4];
            #pragma unroll
            for (int mi = 0; mi < 4; mi++) {
                const int r0 = (wm + mi * 16 + qr) * TSTR + kk + qc;
                afr[mi][0] = __float_as_uint(as[r0]);
                afr[mi][1] = __float_as_uint(as[r0 + 8 * TSTR]);
                afr[mi][2] = __float_as_uint(as[r0 + 4]);
                afr[mi][3] = __float_as_uint(as[r0 + 8 * TSTR + 4]);
            }
            uint32_t bfr[4][2];
            #pragma unroll
            for (int ni = 0; ni < 4; ni++) {
                const int r0 = (wn + ni * 8 + qr) * TSTR + kk + qc;
                bfr[ni][0] = __float_as_uint(bs[r0]);
                bfr[ni][1] = __float_as_uint(bs[r0 + 4]);
            }
            #pragma unroll
            for (int mi = 0; mi < 4; mi++)
                #pragma unroll
                for (int ni = 0; ni < 4; ni++)
                    mma8(acc[mi][ni], afr[mi], bfr[ni]);
        }
        // NOTE: single sync per iter is safe — the sync in iter k+1 orders
        // "compute buf(k)" (all warps) before "store buf(k)" in iter k+2.
    }
    __syncthreads();

    // ---- epilogue: accs -> SMEM staging (stride 132) -> coalesced STG.128 ----
    #pragma unroll
    for (int mi = 0; mi < 4; mi++)
        #pragma unroll
        for (int ni = 0; ni < 4; ni++) {
            const int row = wm + mi * 16 + qr;
            const int col = wn + ni * 8 + qc * 2;
            *(float2*)(sm + row * CSTR + col)       = make_float2(acc[mi][ni][0], acc[mi][ni][1]);
            *(float2*)(sm + (row + 8) * CSTR + col) = make_float2(acc[mi][ni][2], acc[mi][ni][3]);
        }
    __syncthreads();

    const int rr = tid >> 5;           // 0..7
    const int cc = (tid & 31) * 4;     // 0..124
    #pragma unroll
    for (int p = 0; p < 16; p++) {
        const int row = p * 8 + rr;
        const long long gm = m0 + row;
        const int gn = n0 + cc;
        float4 v = *(float4*)(sm + row * CSTR + cc);
        v.x *= scale; v.y *= scale; v.z *= scale; v.w *= scale;
        if (BN_) { v.x += bias[gn]; v.y += bias[gn+1]; v.z += bias[gn+2]; v.w += bias[gn+3]; }
        if (BM_) { const float bm = bias[gm]; v.x += bm; v.y += bm; v.z += bm; v.w += bm; }
        if (ADD_) {
            const float4 ad = *(const float4*)(Add + gm * ldc + gn);
            v.x += ad.x; v.y += ad.y; v.z += ad.z; v.w += ad.w;
        }
        *(float4*)(C + gm * ldc + gn) = v;
    }
}

// Row softmax, one block (256 threads) per row.
__global__ __launch_bounds__(256)
void softmax_rows(float* __restrict__ S, int ncols)
{
    long long row = blockIdx.x;
    float* p = S + row * (long long)ncols;
    __shared__ float red[256];
    const int tid = threadIdx.x;

    float m = -3.4e38f;
    for (int i = tid; i < ncols; i += 256) m = fmaxf(m, p[i]);
    red[tid] = m; __syncthreads();
    #pragma unroll
    for (int s = 128; s > 0; s >>= 1) {
        if (tid < s) red[tid] = fmaxf(red[tid], red[tid + s]);
        __syncthreads();
    }
    m = red[0];
    __syncthreads();

    float sum = 0.f;
    for (int i = tid; i < ncols; i += 256) {
        float e = __expf(p[i] - m);
        p[i] = e;
        sum += e;
    }
    red[tid] = sum; __syncthreads();
    #pragma unroll
    for (int s = 128; s > 0; s >>= 1) {
        if (tid < s) red[tid] += red[tid + s];
        __syncthreads();
    }
    float inv = 1.0f / red[0];
    for (int i = tid; i < ncols; i += 256) p[i] *= inv;
}

extern "C" void kernel_launch(void* const* d_in, const int* in_sizes, int n_in,
                              void* d_out, int out_size)
{
    const float* x  = (const float*)d_in[0];
    const float* ce = (const float*)d_in[1];
    const float* Wq = (const float*)d_in[2];
    const float* bq = (const float*)d_in[3];
    const float* Wk = (const float*)d_in[4];
    const float* bk = (const float*)d_in[5];
    const float* Wv = (const float*)d_in[6];
    const float* bv = (const float*)d_in[7];
    const float* Wo = (const float*)d_in[8];
    const float* bo = (const float*)d_in[9];
    float* out = (float*)d_out;

    float *Q, *K, *Vt, *S, *At;
    cudaGetSymbolAddress((void**)&Q,  g_Q);
    cudaGetSymbolAddress((void**)&K,  g_K);
    cudaGetSymbolAddress((void**)&Vt, g_Vt);
    cudaGetSymbolAddress((void**)&S,  g_S);
    cudaGetSymbolAddress((void**)&At, g_At);

    cudaFuncSetAttribute(gemm_mma<true ,false,false>, cudaFuncAttributeMaxDynamicSharedMemorySize, SMEM_BYTES);
    cudaFuncSetAttribute(gemm_mma<false,true ,false>, cudaFuncAttributeMaxDynamicSharedMemorySize, SMEM_BYTES);
    cudaFuncSetAttribute(gemm_mma<false,false,false>, cudaFuncAttributeMaxDynamicSharedMemorySize, SMEM_BYTES);
    cudaFuncSetAttribute(gemm_mma<false,false,true >, cudaFuncAttributeMaxDynamicSharedMemorySize, SMEM_BYTES);

    const int M = Bdim * SQdim;            // 8192
    dim3 blk(256);

    // Q = x @ Wq^T + bq
    gemm_mma<true,false,false><<<dim3(Cdim/128, M/128, 1), blk, SMEM_BYTES>>>(
        x, Wq, bq, nullptr, Q, Cdim, Cdim, Cdim, Cdim/32, 0,0,0,0, 1.0f);
    // K = ce @ Wk^T + bk
    gemm_mma<true,false,false><<<dim3(Cdim/128, M/128, 1), blk, SMEM_BYTES>>>(
        ce, Wk, bk, nullptr, K, Cdim, Cdim, Cdim, Cdim/32, 0,0,0,0, 1.0f);
    // Vt = Wv @ ce^T + bv   ([C, B*SKV], row-bias)
    gemm_mma<false,true,false><<<dim3(M/128, Cdim/128, 1), blk, SMEM_BYTES>>>(
        Wv, ce, bv, nullptr, Vt, Cdim, Cdim, M, Cdim/32, 0,0,0,0, 1.0f);
    // S = (Q @ K^T) / 32   (batched)
    gemm_mma<false,false,false><<<dim3(SKVdim/128, SQdim/128, Bdim), blk, SMEM_BYTES>>>(
        Q, K, nullptr, nullptr, S, Cdim, Cdim, SKVdim, Cdim/32,
        (long long)SQdim*Cdim, (long long)SKVdim*Cdim, (long long)SQdim*SKVdim, 0, 0.03125f);
    // P = softmax(S)
    softmax_rows<<<Bdim * SQdim, blk>>>(S, SKVdim);
    // At = P @ Vt^T + x   (batched; Vt rows stride 8192, per-batch col offset 2048)
    gemm_mma<false,false,true><<<dim3(Cdim/128, SQdim/128, Bdim), blk, SMEM_BYTES>>>(
        S, Vt, nullptr, x, At, SKVdim, M, Cdim, SKVdim/32,
        (long long)SQdim*SKVdim, (long long)SKVdim, (long long)SQdim*Cdim,
        (long long)SQdim*Cdim, 1.0f);
    // out = At @ Wo^T + bo
    gemm_mma<true,false,false><<<dim3(Cdim/128, M/128, 1), blk, SMEM_BYTES>>>(
        At, Wo, bo, nullptr, out, Cdim, Cdim, Cdim, Cdim/32, 0,0,0,0, 1.0f);
}